// round 17
// baseline (speedup 1.0000x reference)
#include <cuda_runtime.h>
#include <cuda_fp16.h>
#include <cstdint>
#include <cstddef>

// ============================================================================
// S6 reduced:  y[t,d] = x[t,d] * softplus((x@W1^T)[t,d] + b1[d]) * s[t]
//              s[t]   = sum_n (x@W2^T+b2)[t,n] * (x@W3^T+b3)[t,n]
// (h0 == 0 kills the exp(dA) term exactly; A unused.)
// T=4096, d=1024, n=16.
// Main: fp16 mma + fp32 accum, double-buffered ldmatrix, BK=64, 3-stage
//       cp.async; epilogue reads x from fp16 scratch (L2-hot).
// s:    256 CTAs, 16 tokens/CTA, warp = K-quarter, smem reduction;
//       x->fp16 and W1->fp16 conversions fused in.
// ============================================================================

#define MAX_T   4096
#define D_MODEL 1024

__device__ float g_s[MAX_T];
__device__ __align__(16) __half g_xh [MAX_T * D_MODEL];
__device__ __align__(16) __half g_w1h[D_MODEL * D_MODEL];

// ---------------------------------------------------------------------------
// helpers
// ---------------------------------------------------------------------------
__device__ __forceinline__ float tf32r(float f) {
    uint32_t r; asm("cvt.rna.tf32.f32 %0, %1;" : "=r"(r) : "f"(f));
    return __uint_as_float(r);
}
__device__ __forceinline__ float softplus_f(float z) {
    return fmaxf(z, 0.0f) + __logf(1.0f + __expf(-fabsf(z)));
}
__device__ __forceinline__ void mma_tf32(float& c0, float& c1, float& c2, float& c3,
                                         float a0, float a1, float a2, float a3,
                                         float b0, float b1) {
    asm volatile(
        "mma.sync.aligned.m16n8k8.row.col.f32.tf32.tf32.f32 "
        "{%0,%1,%2,%3}, {%4,%5,%6,%7}, {%8,%9}, {%0,%1,%2,%3};\n"
        : "+f"(c0), "+f"(c1), "+f"(c2), "+f"(c3)
        : "r"(__float_as_uint(a0)), "r"(__float_as_uint(a1)),
          "r"(__float_as_uint(a2)), "r"(__float_as_uint(a3)),
          "r"(__float_as_uint(b0)), "r"(__float_as_uint(b1)));
}
__device__ __forceinline__ void mma_f16(float& c0, float& c1, float& c2, float& c3,
                                        uint32_t a0, uint32_t a1, uint32_t a2, uint32_t a3,
                                        uint32_t b0, uint32_t b1) {
    asm volatile(
        "mma.sync.aligned.m16n8k16.row.col.f32.f16.f16.f32 "
        "{%0,%1,%2,%3}, {%4,%5,%6,%7}, {%8,%9}, {%0,%1,%2,%3};\n"
        : "+f"(c0), "+f"(c1), "+f"(c2), "+f"(c3)
        : "r"(a0), "r"(a1), "r"(a2), "r"(a3), "r"(b0), "r"(b1));
}
__device__ __forceinline__ void ldsm4(uint32_t* r, uint32_t addr) {
    asm volatile("ldmatrix.sync.aligned.m8n8.x4.shared.b16 {%0,%1,%2,%3}, [%4];"
                 : "=r"(r[0]), "=r"(r[1]), "=r"(r[2]), "=r"(r[3]) : "r"(addr));
}
__device__ __forceinline__ void cp16(uint32_t dst_smem, const void* src) {
    asm volatile("cp.async.cg.shared.global [%0], [%1], 16;"
                 :: "r"(dst_smem), "l"(src));
}
__device__ __forceinline__ void cp_commit() {
    asm volatile("cp.async.commit_group;");
}
template <int N>
__device__ __forceinline__ void cp_wait() {
    asm volatile("cp.async.wait_group %0;" :: "n"(N) : "memory");
}

// ---------------------------------------------------------------------------
// s_kernel v3: Z2 = X @ [W2;W3]^T, 16 tokens/CTA, grid = T/16 = 256 CTAs.
// 4 warps = 4 K-quarters (256 K each, advancing 32/slab, 8 slabs).
// Stage: A 16x128 f32 (8KB, 4 quarter blocks of 16x32) +
//        W 32x128 f32 (16KB, 4 quarter blocks of 32x32) = 24KB, 4 stages.
// Partial accs reduced across quarters via smem; s via pair-product + shfl.
// FUSED: x->fp16 (from staged tiles) and W1->fp16 (1 float4/thread/slab).
// ---------------------------------------------------------------------------
#define SS   4
#define SSTG 24576

__global__ __launch_bounds__(128, 2) void s_kernel(
    const float* __restrict__ x,
    const float* __restrict__ W2, const float* __restrict__ b2,
    const float* __restrict__ W3, const float* __restrict__ b3,
    const float* __restrict__ W1,
    int T, int d)
{
    extern __shared__ float smemf[];
    uint32_t sbase = (uint32_t)__cvta_generic_to_shared(smemf);

    int tid  = threadIdx.x;
    int lane = tid & 31;
    int w    = tid >> 5;          // K quarter: k in [w*256, w*256+256)
    int gid  = lane >> 2;
    int tig  = lane & 3;
    int t0   = blockIdx.x * 16;

    // ---- A chunk geometry: 4 float4/thread/slab ----
    int aq[4], ar[4], ac[4]; uint32_t aoff[4];
    const float* asrc[4];
    #pragma unroll
    for (int j = 0; j < 4; j++) {
        int id = tid + 128 * j;               // 0..511
        aq[j] = id >> 7;                       // quarter
        ar[j] = (id >> 3) & 15;                // row 0..15
        ac[j] = (id & 7) * 4;                  // col4 0..28
        aoff[j] = (uint32_t)((aq[j] * 512 + ar[j] * 32
                   + (ac[j] ^ ((ar[j] & 7) << 2))) * 4);
        asrc[j] = x + (size_t)(t0 + ar[j]) * d + aq[j] * 256 + ac[j];
    }
    // ---- W chunk geometry: 8 float4/thread/slab ----
    uint32_t woff[8];
    const float* wsrc[8];
    #pragma unroll
    for (int j = 0; j < 8; j++) {
        int id = tid + 128 * j;               // 0..1023
        int q  = id >> 8;                      // quarter
        int r  = (id >> 3) & 31;               // row 0..31
        int c4 = (id & 7) * 4;
        woff[j] = (uint32_t)((2048 + q * 1024 + r * 32
                   + (c4 ^ ((r & 7) << 2))) * 4);
        const float* base = (r < 16) ? (W2 + (size_t)r * d)
                                     : (W3 + (size_t)(r - 16) * d);
        wsrc[j] = base + q * 256 + c4;
    }

    float acc[4][4];
    #pragma unroll
    for (int i = 0; i < 4; i++)
        #pragma unroll
        for (int c = 0; c < 4; c++) acc[i][c] = 0.f;

    const int nslab = d / 128;                // 8
    const int ntt   = (T / 16) * 128;         // 32768
    int gtid = blockIdx.x * 128 + tid;

    #pragma unroll
    for (int j = 0; j < SS - 1; j++) {
        uint32_t sa = sbase + (uint32_t)(j * SSTG);
        int k0 = j * 32;
        #pragma unroll
        for (int q = 0; q < 4; q++) cp16(sa + aoff[q], asrc[q] + k0);
        #pragma unroll
        for (int q = 0; q < 8; q++) cp16(sa + woff[q], wsrc[q] + k0);
        cp_commit();
    }

    int xr = gid << 2;

    for (int i = 0; i < nslab; i++) {
        cp_wait<SS - 2>();
        __syncthreads();

        int jn = i + SS - 1;
        if (jn < nslab) {
            uint32_t sa = sbase + (uint32_t)((jn % SS) * SSTG);
            int k0 = jn * 32;
            #pragma unroll
            for (int q = 0; q < 4; q++) cp16(sa + aoff[q], asrc[q] + k0);
            #pragma unroll
            for (int q = 0; q < 8; q++) cp16(sa + woff[q], wsrc[q] + k0);
        }
        cp_commit();

        // ---- fused W1 -> fp16: one float4 per thread per slab ----
        {
            int idx = i * ntt + gtid;          // covers d*d/4 = 262144
            float4 v = ((const float4*)W1)[idx];
            __half2 h0 = __floats2half2_rn(v.x, v.y);
            __half2 h1 = __floats2half2_rn(v.z, v.w);
            uint2 pk;
            pk.x = *(uint32_t*)&h0;
            pk.y = *(uint32_t*)&h1;
            ((uint2*)g_w1h)[idx] = pk;
        }

        const float* St = smemf + (size_t)(i % SS) * (SSTG / 4);
        int k0 = i * 32;

        // ---- fused x -> fp16 from staged A tiles ----
        #pragma unroll
        for (int j = 0; j < 4; j++) {
            float4 v = *(const float4*)((const char*)St + aoff[j]);
            __half2 h0 = __floats2half2_rn(v.x, v.y);
            __half2 h1 = __floats2half2_rn(v.z, v.w);
            uint2 pk;
            pk.x = *(uint32_t*)&h0;
            pk.y = *(uint32_t*)&h1;
            *(uint2*)(g_xh + (size_t)(t0 + ar[j]) * d
                      + aq[j] * 256 + k0 + ac[j]) = pk;
        }

        const float* As = St + w * 512;            // warp's A quarter block
        const float* Ws = St + 2048 + w * 1024;    // warp's W quarter block

        #pragma unroll
        for (int kk = 0; kk < 32; kk += 8) {
            int c1 = (kk + tig) ^ xr;
            int c2 = (kk + tig + 4) ^ xr;
            float a0 = tf32r(As[gid * 32 + c1]);
            float a1 = tf32r(As[(gid + 8) * 32 + c1]);
            float a2 = tf32r(As[gid * 32 + c2]);
            float a3 = tf32r(As[(gid + 8) * 32 + c2]);
            #pragma unroll
            for (int ni = 0; ni < 4; ni++) {
                int n = ni * 8 + gid;
                float b0  = tf32r(Ws[n * 32 + c1]);
                float b1v = tf32r(Ws[n * 32 + c2]);
                mma_tf32(acc[ni][0], acc[ni][1], acc[ni][2], acc[ni][3],
                         a0, a1, a2, a3, b0, b1v);
            }
        }
    }

    // ---- reduce K-quarters via smem (all cp.async drained first) ----
    cp_wait<0>();
    __syncthreads();
    float* sred = smemf;    // 3 warps x 16 vals x 32 lanes = 6KB
    if (w > 0) {
        #pragma unroll
        for (int ni = 0; ni < 4; ni++)
            #pragma unroll
            for (int c = 0; c < 4; c++)
                sred[(w - 1) * 512 + (ni * 4 + c) * 32 + lane] = acc[ni][c];
    }
    __syncthreads();
    if (w == 0) {
        #pragma unroll
        for (int ni = 0; ni < 4; ni++)
            #pragma unroll
            for (int c = 0; c < 4; c++) {
                int o = (ni * 4 + c) * 32 + lane;
                acc[ni][c] += sred[o] + sred[512 + o] + sred[1024 + o];
            }

        // s = sum_n (Z[:,n]+b2[n]) * (Z[:,n+16]+b3[n])
        int nb0 = tig * 2, nb1 = nb0 + 1, nb2 = nb0 + 8, nb3 = nb0 + 9;
        float p2[4] = {b2[nb0], b2[nb1], b2[nb2], b2[nb3]};
        float p3[4] = {b3[nb0], b3[nb1], b3[nb2], b3[nb3]};

        #pragma unroll
        for (int h = 0; h < 2; h++) {
            float p =
                (acc[0][h*2+0] + p2[0]) * (acc[2][h*2+0] + p3[0]) +
                (acc[0][h*2+1] + p2[1]) * (acc[2][h*2+1] + p3[1]) +
                (acc[1][h*2+0] + p2[2]) * (acc[3][h*2+0] + p3[2]) +
                (acc[1][h*2+1] + p2[3]) * (acc[3][h*2+1] + p3[3]);
            p += __shfl_xor_sync(0xffffffffu, p, 1);
            p += __shfl_xor_sync(0xffffffffu, p, 2);
            if (tig == 0) {
                int t = t0 + gid + h * 8;
                if (t < T) g_s[t] = p;
            }
        }
    }
}

// ---------------------------------------------------------------------------
// main_kernel: Z = X @ W1^T (fp16 in, fp32 accum), y = x*softplus(Z+b1)*s.
// BM=BN=128, BK=64. 4 warps (2x2), warp tile 64x64, swizzle p = c ^ (r&7).
// 3-stage pipeline, 2 CTAs/SM, double-buffered fragments, cp.async
// interleaved into the mma loop.  Epilogue x comes from g_xh (fp16, L2-hot).
// ---------------------------------------------------------------------------
#define MS   3
#define MSTG 32768

__global__ __launch_bounds__(128, 2) void main_kernel(
    const float* __restrict__ b1, float* __restrict__ y, int T, int d)
{
    extern __shared__ char smem[];
    uint32_t sbase = (uint32_t)__cvta_generic_to_shared(smem);

    int tid  = threadIdx.x;
    int lane = tid & 31;
    int warp = tid >> 5;
    int wm   = warp >> 1;
    int wn   = warp & 1;
    int gid  = lane >> 2;
    int tig  = lane & 3;

    int bm = blockIdx.x * 128;
    int bn = blockIdx.y * 128;

    int q    = tid & 7;
    int rowb = tid >> 3;
    uint32_t soff[8];
    #pragma unroll
    for (int j = 0; j < 8; j++) {
        int r = rowb + 16 * j;
        soff[j] = (uint32_t)(r * 128 + ((q ^ (r & 7)) << 4));
    }
    const __half* aptr = g_xh  + (size_t)(bm + rowb) * d + q * 8;
    const __half* bptr = g_w1h + (size_t)(bn + rowb) * d + q * 8;

    int g = lane >> 3, lrow8 = lane & 7;
    uint32_t abase[4]; int axor[4];
    #pragma unroll
    for (int mi = 0; mi < 4; mi++) {
        int r = wm * 64 + mi * 16 + (g & 1) * 8 + lrow8;
        abase[mi] = (uint32_t)(r * 128);
        axor[mi]  = r & 7;
    }
    int acb = g >> 1;
    uint32_t bbase[4]; int bxor[4];
    #pragma unroll
    for (int nb = 0; nb < 4; nb++) {
        int r = wn * 64 + nb * 16 + (g >> 1) * 8 + lrow8;
        bbase[nb] = (uint32_t)(r * 128);
        bxor[nb]  = r & 7;
    }
    int bcb = g & 1;

    float acc[4][8][4];
    #pragma unroll
    for (int mi = 0; mi < 4; mi++)
        #pragma unroll
        for (int nj = 0; nj < 8; nj++)
            #pragma unroll
            for (int c = 0; c < 4; c++) acc[mi][nj][c] = 0.f;

    const int nslab = d / 64;      // 16

    #pragma unroll
    for (int j = 0; j < MS - 1; j++) {
        uint32_t sa = sbase + (uint32_t)(j * MSTG);
        uint32_t sb = sa + 16384u;
        int k0 = j * 64;
        #pragma unroll
        for (int jj = 0; jj < 8; jj++) {
            cp16(sa + soff[jj], aptr + (size_t)(16 * jj) * d + k0);
            cp16(sb + soff[jj], bptr + (size_t)(16 * jj) * d + k0);
        }
        cp_commit();
    }

    for (int i = 0; i < nslab; i++) {
        cp_wait<MS - 2>();
        __syncthreads();

        int jn = i + MS - 1;
        bool doload = jn < nslab;
        uint32_t nsa = 0, nsb = 0; int nk0 = 0;
        if (doload) {
            nsa = sbase + (uint32_t)((jn % MS) * MSTG);
            nsb = nsa + 16384u;
            nk0 = jn * 64;
        }

        uint32_t sA = sbase + (uint32_t)((i % MS) * MSTG);
        uint32_t sB = sA + 16384u;

        uint32_t abuf[2][4][4], bbuf[2][4][4];
        #pragma unroll
        for (int mi = 0; mi < 4; mi++)
            ldsm4(abuf[0][mi], sA + abase[mi] + (uint32_t)(((acb) ^ axor[mi]) << 4));
        #pragma unroll
        for (int nb = 0; nb < 4; nb++)
            ldsm4(bbuf[0][nb], sB + bbase[nb] + (uint32_t)(((bcb) ^ bxor[nb]) << 4));

        #pragma unroll
        for (int kk = 0; kk < 4; kk++) {
            int cur = kk & 1, nxt = cur ^ 1;
            if (kk < 3) {
                int c2 = (kk + 1) * 2;
                #pragma unroll
                for (int mi = 0; mi < 4; mi++)
                    ldsm4(abuf[nxt][mi], sA + abase[mi] + (uint32_t)((((c2 + acb) ^ axor[mi])) << 4));
                #pragma unroll
                for (int nb = 0; nb < 4; nb++)
                    ldsm4(bbuf[nxt][nb], sB + bbase[nb] + (uint32_t)((((c2 + bcb) ^ bxor[nb])) << 4));
            }
            if (doload) {
                int j0 = kk * 2;
                cp16(nsa + soff[j0],     aptr + (size_t)(16 * j0) * d + nk0);
                cp16(nsa + soff[j0 + 1], aptr + (size_t)(16 * (j0 + 1)) * d + nk0);
                cp16(nsb + soff[j0],     bptr + (size_t)(16 * j0) * d + nk0);
                cp16(nsb + soff[j0 + 1], bptr + (size_t)(16 * (j0 + 1)) * d + nk0);
            }
            #pragma unroll
            for (int mi = 0; mi < 4; mi++)
                #pragma unroll
                for (int nj = 0; nj < 8; nj++)
                    mma_f16(acc[mi][nj][0], acc[mi][nj][1],
                            acc[mi][nj][2], acc[mi][nj][3],
                            abuf[cur][mi][0], abuf[cur][mi][1],
                            abuf[cur][mi][2], abuf[cur][mi][3],
                            bbuf[cur][nj >> 1][(nj & 1) * 2],
                            bbuf[cur][nj >> 1][(nj & 1) * 2 + 1]);
        }
        cp_commit();
    }

    // ---- fused epilogue: y = x * softplus(z + b1) * s  (x from g_xh fp16) ----
    #pragma unroll
    for (int mi = 0; mi < 4; mi++) {
        int r0 = bm + wm * 64 + mi * 16 + gid;
        int r1 = r0 + 8;
        float sv0 = g_s[r0];
        float sv1 = g_s[r1];
        #pragma unroll
        for (int nj = 0; nj < 8; nj++) {
            int c0 = bn + wn * 64 + nj * 8 + tig * 2;
            float2 bias = *(const float2*)&b1[c0];
            float2 x0 = __half22float2(*(const __half2*)(g_xh + (size_t)r0 * d + c0));
            float2 x1 = __half22float2(*(const __half2*)(g_xh + (size_t)r1 * d + c0));
            float2 o0, o1;
            o0.x = x0.x * softplus_f(acc[mi][nj][0] + bias.x) * sv0;
            o0.y = x0.y * softplus_f(acc[mi][nj][1] + bias.y) * sv0;
            o1.x = x1.x * softplus_f(acc[mi][nj][2] + bias.x) * sv1;
            o1.y = x1.y * softplus_f(acc[mi][nj][3] + bias.y) * sv1;
            *(float2*)&y[(size_t)r0 * d + c0] = o0;
            *(float2*)&y[(size_t)r1 * d + c0] = o1;
        }
    }
}

// ---------------------------------------------------------------------------
// launch — inputs (metadata order): x, W1, b1, W2, b2, W3, b3, A
// ---------------------------------------------------------------------------
extern "C" void kernel_launch(void* const* d_in, const int* in_sizes, int n_in,
                              void* d_out, int out_size)
{
    const float* x  = (const float*)d_in[0];
    const float* W1 = (const float*)d_in[1];
    const float* b1 = (const float*)d_in[2];
    const float* W2 = (const float*)d_in[3];
    const float* b2 = (const float*)d_in[4];
    const float* W3 = (const float*)d_in[5];
    const float* b3 = (const float*)d_in[6];
    // d_in[7] = A: unused (h0 == 0 kills exp(dA)*h0 exactly)

    int d = in_sizes[2];          // d_model (1024)
    int T = in_sizes[0] / d;      // tokens (4096)
    float* y = (float*)d_out;

    const int SMEM_MAIN = MS * MSTG;   // 3 * 32KB = 96KB
    const int SMEM_S    = SS * SSTG;   // 4 * 24KB = 96KB

    cudaFuncSetAttribute(main_kernel, cudaFuncAttributeMaxDynamicSharedMemorySize, SMEM_MAIN);
    cudaFuncSetAttribute(s_kernel,    cudaFuncAttributeMaxDynamicSharedMemorySize, SMEM_S);

    s_kernel<<<T / 16, 128, SMEM_S>>>(x, W2, b2, W3, b3, W1, T, d);
    dim3 grid(T / 128, d / 128);
    main_kernel<<<grid, 128, SMEM_MAIN>>>(b1, y, T, d);
}